// round 1
// baseline (speedup 1.0000x reference)
#include <cuda_runtime.h>

#define Nn 50000
#define Ee 800000
#define Hh 128
#define Ll 4
#define Gg 64

// ---------------- scratch (device globals; no allocation allowed) ----------
__device__ float g_h[(size_t)Nn * Hh];     // current node features
__device__ float g_tmp[(size_t)Nn * Hh];   // MLP intermediate
__device__ float g_agg[(size_t)Nn * Hh];   // scatter accumulator
__device__ float g_invdeg[Nn];
__device__ int   g_deg[Nn];
__device__ float g_vn[Gg * Hh];
__device__ float g_vt[Gg * Hh];
__device__ int   g_starts[Gg + 1];

// ---------------- degree ----------------------------------------------------
__global__ void k_deg(const int* __restrict__ tgt) {
    int e = blockIdx.x * blockDim.x + threadIdx.x;
    if (e < Ee) atomicAdd(&g_deg[__ldg(tgt + e)], 1);
}

__global__ void k_invdeg() {
    int n = blockIdx.x * blockDim.x + threadIdx.x;
    if (n < Nn) {
        int d = g_deg[n];
        g_invdeg[n] = 1.0f / (float)(d > 0 ? d : 1);
    }
}

// ---------------- graph segment boundaries (batch is sorted) ---------------
__global__ void k_starts(const int* __restrict__ batch) {
    int n = blockIdx.x * blockDim.x + threadIdx.x;
    if (n >= Nn) return;
    int b = __ldg(batch + n);
    if (n == 0) {
        for (int g = 0; g <= b; g++) g_starts[g] = 0;
    } else {
        int pb = __ldg(batch + n - 1);
        for (int g = pb + 1; g <= b; g++) g_starts[g] = n;
    }
    if (n == Nn - 1) {
        for (int g = b + 1; g <= Gg; g++) g_starts[g] = Nn;
    }
}

// ---------------- virtual node init -----------------------------------------
__global__ void k_vninit(const float* __restrict__ vn_emb) {
    int i = blockIdx.x * blockDim.x + threadIdx.x;
    if (i < Gg * Hh) g_vn[i] = __ldg(vn_emb + (i & (Hh - 1)));
}

// ---------------- h = src + vn[batch] ---------------------------------------
__global__ void k_addvn(const float* __restrict__ xin,
                        const int* __restrict__ batch, int use_x) {
    int i = blockIdx.x * blockDim.x + threadIdx.x;   // over Nn*32 float4 slots
    if (i >= Nn * 32) return;
    int n = i >> 5;
    int q = (i & 31) * 4;
    const float* srcp = use_x ? xin : g_h;
    int b = __ldg(batch + n);
    float4 v = *(const float4*)(srcp + (size_t)n * Hh + q);
    float4 w = *(const float4*)(g_vn + b * Hh + q);
    v.x += w.x; v.y += w.y; v.z += w.z; v.w += w.w;
    *(float4*)(g_h + (size_t)n * Hh + q) = v;
}

// ---------------- edge message + scatter-add --------------------------------
// one warp per edge; lane handles 4 floats (float4). vec4 reduction atomics.
__global__ void k_edge(const int* __restrict__ ei,
                       const float* __restrict__ eattr,
                       const float* __restrict__ eW,
                       const float* __restrict__ eb) {
    int e = blockIdx.x * (blockDim.x >> 5) + (threadIdx.x >> 5);
    if (e >= Ee) return;
    int lane = threadIdx.x & 31;
    int s = __ldg(ei + e);
    int t = __ldg(ei + Ee + e);
    float a = __ldg(eattr + e);
    float4 w  = *(const float4*)(eW + lane * 4);
    float4 bb = *(const float4*)(eb + lane * 4);
    float4 h4 = *(const float4*)(g_h + (size_t)s * Hh + lane * 4);
    float4 m;
    m.x = fmaxf(h4.x + fmaf(a, w.x, bb.x), 0.0f);
    m.y = fmaxf(h4.y + fmaf(a, w.y, bb.y), 0.0f);
    m.z = fmaxf(h4.z + fmaf(a, w.z, bb.z), 0.0f);
    m.w = fmaxf(h4.w + fmaf(a, w.w, bb.w), 0.0f);
    float* dst = g_agg + (size_t)t * Hh + lane * 4;
    asm volatile("red.global.add.v4.f32 [%0], {%1, %2, %3, %4};"
                 :: "l"(dst), "f"(m.x), "f"(m.y), "f"(m.z), "f"(m.w)
                 : "memory");
}

// ---------------- 128x128 GEMM over N rows ----------------------------------
// phase 0: A = (1+eps)*h + agg*invdeg (fused), C = relu(A@W1 + b1) -> g_tmp
// phase 1: A = g_tmp,                 C = A@W2 + b2 -> g_h and d_out block
#define TM  64
#define TMP 68   // padded transposed-A leading dim

__global__ void __launch_bounds__(256, 2)
k_gemm(int phase, const float* __restrict__ epsPtr,
       const float* __restrict__ W, const float* __restrict__ bias,
       float* __restrict__ C2, int c2off) {
    extern __shared__ float sm[];
    float* Ws = sm;                  // [128][128]
    float* As = sm + 128 * 128;      // transposed: [128][TMP]
    int tid = threadIdx.x;

    // stage weights (64 KB)
    {
        const float4* Wg = (const float4*)W;
        float4* Wsv = (float4*)Ws;
        #pragma unroll
        for (int i = 0; i < 16; i++) Wsv[tid + 256 * i] = Wg[tid + 256 * i];
    }

    int row0 = blockIdx.x * TM;
    // stage A tile transposed; fuse z-computation in phase 0
    {
        int r  = tid >> 2;
        int c0 = (tid & 3) * 32;
        int grow = row0 + r;
        if (grow < Nn) {
            const float* Ar = (phase ? g_tmp : g_h) + (size_t)grow * Hh + c0;
            float ep = 0.0f, idg = 0.0f;
            const float* Gr = g_agg + (size_t)grow * Hh + c0;
            if (phase == 0) { ep = 1.0f + __ldg(epsPtr); idg = g_invdeg[grow]; }
            #pragma unroll
            for (int j = 0; j < 8; j++) {
                float4 v = *(const float4*)(Ar + j * 4);
                if (phase == 0) {
                    float4 g4 = *(const float4*)(Gr + j * 4);
                    v.x = fmaf(ep, v.x, g4.x * idg);
                    v.y = fmaf(ep, v.y, g4.y * idg);
                    v.z = fmaf(ep, v.z, g4.z * idg);
                    v.w = fmaf(ep, v.w, g4.w * idg);
                }
                int c = c0 + j * 4;
                As[(c + 0) * TMP + r] = v.x;
                As[(c + 1) * TMP + r] = v.y;
                As[(c + 2) * TMP + r] = v.z;
                As[(c + 3) * TMP + r] = v.w;
            }
        } else {
            #pragma unroll
            for (int j = 0; j < 32; j++) As[(c0 + j) * TMP + r] = 0.0f;
        }
    }
    __syncthreads();

    int tr = tid >> 4, tc = tid & 15;        // 16x16 threads; 4 rows x 8 cols each
    float acc[4][8];
    #pragma unroll
    for (int i = 0; i < 4; i++)
        #pragma unroll
        for (int j = 0; j < 8; j++) acc[i][j] = 0.0f;

    #pragma unroll 8
    for (int k = 0; k < 128; k++) {
        float4 a  = *(const float4*)&As[k * TMP + tr * 4];
        float4 b0 = *(const float4*)&Ws[k * 128 + tc * 4];
        float4 b1 = *(const float4*)&Ws[k * 128 + 64 + tc * 4];
        float av[4] = {a.x, a.y, a.z, a.w};
        float bv[8] = {b0.x, b0.y, b0.z, b0.w, b1.x, b1.y, b1.z, b1.w};
        #pragma unroll
        for (int i = 0; i < 4; i++)
            #pragma unroll
            for (int j = 0; j < 8; j++)
                acc[i][j] = fmaf(av[i], bv[j], acc[i][j]);
    }

    float* Cp = phase ? g_h : g_tmp;
    float4 bb0 = *(const float4*)(bias + tc * 4);
    float4 bb1 = *(const float4*)(bias + 64 + tc * 4);
    int do_relu = (phase == 0);
    #pragma unroll
    for (int i = 0; i < 4; i++) {
        int grow = row0 + tr * 4 + i;
        if (grow < Nn) {
            float4 o0, o1;
            o0.x = acc[i][0] + bb0.x; o0.y = acc[i][1] + bb0.y;
            o0.z = acc[i][2] + bb0.z; o0.w = acc[i][3] + bb0.w;
            o1.x = acc[i][4] + bb1.x; o1.y = acc[i][5] + bb1.y;
            o1.z = acc[i][6] + bb1.z; o1.w = acc[i][7] + bb1.w;
            if (do_relu) {
                o0.x = fmaxf(o0.x, 0.f); o0.y = fmaxf(o0.y, 0.f);
                o0.z = fmaxf(o0.z, 0.f); o0.w = fmaxf(o0.w, 0.f);
                o1.x = fmaxf(o1.x, 0.f); o1.y = fmaxf(o1.y, 0.f);
                o1.z = fmaxf(o1.z, 0.f); o1.w = fmaxf(o1.w, 0.f);
            }
            *(float4*)(Cp + (size_t)grow * Hh + tc * 4)       = o0;
            *(float4*)(Cp + (size_t)grow * Hh + 64 + tc * 4)  = o1;
            if (C2) {
                *(float4*)(C2 + (size_t)grow * (Ll * Hh) + c2off + tc * 4)      = o0;
                *(float4*)(C2 + (size_t)grow * (Ll * Hh) + c2off + 64 + tc * 4) = o1;
            }
        }
    }
}

// ---------------- vt[g] = sum_{n in graph g} h[n] + vn[g] -------------------
__global__ void k_vt() {
    int g = blockIdx.x;
    int c = threadIdx.x;   // 128 threads
    int s = g_starts[g], e = g_starts[g + 1];
    float acc = 0.0f;
    int n = s;
    for (; n + 4 <= e; n += 4) {
        acc += __ldg(&g_h[(size_t)(n + 0) * Hh + c]);
        acc += __ldg(&g_h[(size_t)(n + 1) * Hh + c]);
        acc += __ldg(&g_h[(size_t)(n + 2) * Hh + c]);
        acc += __ldg(&g_h[(size_t)(n + 3) * Hh + c]);
    }
    for (; n < e; n++) acc += __ldg(&g_h[(size_t)n * Hh + c]);
    g_vt[g * Hh + c] = acc + g_vn[g * Hh + c];
}

// ---------------- virtual-node two-layer MLP (fused) ------------------------
__global__ void k_vnmlp(const float* __restrict__ W1, const float* __restrict__ b1,
                        const float* __restrict__ W2, const float* __restrict__ b2) {
    __shared__ float vrow[128];
    __shared__ float trow[128];
    int g = blockIdx.x, c = threadIdx.x;
    vrow[c] = g_vt[g * Hh + c];
    __syncthreads();
    float acc = __ldg(b1 + c);
    #pragma unroll 8
    for (int k = 0; k < 128; k++) acc = fmaf(vrow[k], __ldg(W1 + k * 128 + c), acc);
    trow[c] = fmaxf(acc, 0.0f);
    __syncthreads();
    float acc2 = __ldg(b2 + c);
    #pragma unroll 8
    for (int k = 0; k < 128; k++) acc2 = fmaf(trow[k], __ldg(W2 + k * 128 + c), acc2);
    g_vn[g * Hh + c] = fmaxf(acc2, 0.0f);
}

// ---------------- launcher ---------------------------------------------------
extern "C" void kernel_launch(void* const* d_in, const int* in_sizes, int n_in,
                              void* d_out, int out_size) {
    const float* x         = (const float*)d_in[0];
    const float* edge_attr = (const float*)d_in[1];
    const float* conv_W1   = (const float*)d_in[2];
    const float* conv_b1   = (const float*)d_in[3];
    const float* conv_W2   = (const float*)d_in[4];
    const float* conv_b2   = (const float*)d_in[5];
    const float* conv_eps  = (const float*)d_in[6];
    const float* edge_W    = (const float*)d_in[7];
    const float* edge_b    = (const float*)d_in[8];
    const float* vn_W1     = (const float*)d_in[9];
    const float* vn_b1     = (const float*)d_in[10];
    const float* vn_W2     = (const float*)d_in[11];
    const float* vn_b2     = (const float*)d_in[12];
    const float* vn_emb    = (const float*)d_in[13];
    const int*   edge_index= (const int*)d_in[14];
    const int*   batch     = (const int*)d_in[15];
    float* out = (float*)d_out;

    (void)in_sizes; (void)n_in; (void)out_size;

    void *p_deg = nullptr, *p_agg = nullptr;
    cudaGetSymbolAddress(&p_deg, g_deg);
    cudaGetSymbolAddress(&p_agg, g_agg);

    const int smem_bytes = (128 * 128 + 128 * TMP) * (int)sizeof(float);
    cudaFuncSetAttribute(k_gemm, cudaFuncAttributeMaxDynamicSharedMemorySize,
                         smem_bytes);

    // degree (once per call; tgt is fixed)
    cudaMemsetAsync(p_deg, 0, Nn * sizeof(int), 0);
    k_deg<<<(Ee + 255) / 256, 256>>>(edge_index + Ee);
    k_invdeg<<<(Nn + 255) / 256, 256>>>();
    k_starts<<<(Nn + 255) / 256, 256>>>(batch);
    k_vninit<<<(Gg * Hh + 255) / 256, 256>>>(vn_emb);

    const int gemm_grid = (Nn + TM - 1) / TM;

    for (int i = 0; i < Ll; i++) {
        // h = (i==0 ? x : h) + vn[batch]
        k_addvn<<<(Nn * 32 + 255) / 256, 256>>>(x, batch, i == 0 ? 1 : 0);
        // agg = 0
        cudaMemsetAsync(p_agg, 0, (size_t)Nn * Hh * sizeof(float), 0);
        // scatter messages
        k_edge<<<(Ee + 7) / 8, 256>>>(edge_index, edge_attr,
                                      edge_W + i * Hh, edge_b + i * Hh);
        // tmp = relu(((1+eps)h + agg/deg) @ W1 + b1)
        k_gemm<<<gemm_grid, 256, smem_bytes>>>(0, conv_eps + i,
                                               conv_W1 + (size_t)i * Hh * Hh,
                                               conv_b1 + i * Hh, nullptr, 0);
        // h = tmp @ W2 + b2 ; also write JK output block
        k_gemm<<<gemm_grid, 256, smem_bytes>>>(1, conv_eps + i,
                                               conv_W2 + (size_t)i * Hh * Hh,
                                               conv_b2 + i * Hh, out, i * Hh);
        if (i < Ll - 1) {
            k_vt<<<Gg, Hh>>>();
            k_vnmlp<<<Gg, Hh>>>(vn_W1 + (size_t)i * Hh * Hh, vn_b1 + i * Hh,
                                vn_W2 + (size_t)i * Hh * Hh, vn_b2 + i * Hh);
        }
    }
}

// round 3
// speedup vs baseline: 1.0672x; 1.0672x over previous
#include <cuda_runtime.h>
#include <cstdint>

#define Nn 50000
#define Ee 800000
#define Hh 128
#define Ll 4
#define Gg 64

// ---------------- scratch (device globals; no allocation allowed) ----------
__device__ float g_h[(size_t)Nn * Hh];     // current node features
__device__ float g_tmp[(size_t)Nn * Hh];   // MLP intermediate
__device__ float g_agg[(size_t)Nn * Hh];   // scatter accumulator
__device__ float g_invdeg[Nn];
__device__ int   g_deg[Nn];
__device__ float g_vn[Gg * Hh];
__device__ float g_vt[Gg * Hh];
__device__ int   g_starts[Gg + 1];

// ---------------- degree ----------------------------------------------------
__global__ void k_deg(const int* __restrict__ tgt) {
    int e = blockIdx.x * blockDim.x + threadIdx.x;
    if (e < Ee) atomicAdd(&g_deg[__ldg(tgt + e)], 1);
}

// ---------------- fused setup: invdeg + segment starts + vn init ------------
__global__ void k_setup(const int* __restrict__ batch,
                        const float* __restrict__ vn_emb) {
    int n = blockIdx.x * blockDim.x + threadIdx.x;
    if (n < Nn) {
        int d = g_deg[n];
        g_invdeg[n] = 1.0f / (float)(d > 0 ? d : 1);
        int b = __ldg(batch + n);
        if (n == 0) {
            for (int g = 0; g <= b; g++) g_starts[g] = 0;
        } else {
            int pb = __ldg(batch + n - 1);
            for (int g = pb + 1; g <= b; g++) g_starts[g] = n;
        }
        if (n == Nn - 1)
            for (int g = b + 1; g <= Gg; g++) g_starts[g] = Nn;
    }
    if (n < Gg * Hh) g_vn[n] = __ldg(vn_emb + (n & (Hh - 1)));
}

// ---------------- h = src + vn[batch] ---------------------------------------
__global__ void k_addvn(const float* __restrict__ xin,
                        const int* __restrict__ batch, int use_x) {
    int i = blockIdx.x * blockDim.x + threadIdx.x;   // over Nn*32 float4 slots
    if (i >= Nn * 32) return;
    int n = i >> 5;
    int q = (i & 31) * 4;
    const float* srcp = use_x ? xin : g_h;
    int b = __ldg(batch + n);
    float4 v = *(const float4*)(srcp + (size_t)n * Hh + q);
    float4 w = *(const float4*)(g_vn + b * Hh + q);
    v.x += w.x; v.y += w.y; v.z += w.z; v.w += w.w;
    *(float4*)(g_h + (size_t)n * Hh + q) = v;
}

// ---------------- edge message + scatter-add --------------------------------
__global__ void k_edge(const int* __restrict__ ei,
                       const float* __restrict__ eattr,
                       const float* __restrict__ eW,
                       const float* __restrict__ eb) {
    int e = blockIdx.x * (blockDim.x >> 5) + (threadIdx.x >> 5);
    if (e >= Ee) return;
    int lane = threadIdx.x & 31;
    int s = __ldg(ei + e);
    int t = __ldg(ei + Ee + e);
    float a = __ldg(eattr + e);
    float4 w  = *(const float4*)(eW + lane * 4);
    float4 bb = *(const float4*)(eb + lane * 4);
    float4 h4 = *(const float4*)(g_h + (size_t)s * Hh + lane * 4);
    float4 m;
    m.x = fmaxf(h4.x + fmaf(a, w.x, bb.x), 0.0f);
    m.y = fmaxf(h4.y + fmaf(a, w.y, bb.y), 0.0f);
    m.z = fmaxf(h4.z + fmaf(a, w.z, bb.z), 0.0f);
    m.w = fmaxf(h4.w + fmaf(a, w.w, bb.w), 0.0f);
    float* dst = g_agg + (size_t)t * Hh + lane * 4;
    asm volatile("red.global.add.v4.f32 [%0], {%1, %2, %3, %4};"
                 :: "l"(dst), "f"(m.x), "f"(m.y), "f"(m.z), "f"(m.w)
                 : "memory");
}

// ================= 3xTF32 split GEMM via mma.sync ===========================
// D[128,128] = A[128,128] @ W[128,128], A/B split into tf32 hi + tf32 lo.
// phase 0: A = (1+eps)*h + agg*invdeg (fused), C = relu(A@W1+b1) -> g_tmp
// phase 1: A = g_tmp, C = A@W2+b2 -> g_h and JK output block
#define PADA 68    // 68 mod 32 = 4 -> rows spread banks (A frag LDS conflict-free)
#define PADB 136   // 136 mod 32 = 8 -> k rows spread banks (B frag conflict-free)

__device__ __forceinline__ uint32_t to_tf32(float z) {
    uint32_t h;
    asm("cvt.rna.tf32.f32 %0, %1;" : "=r"(h) : "f"(z));
    return h;
}
__device__ __forceinline__ void split_tf32(float z, float& hi, float& lo) {
    uint32_t h = to_tf32(z);
    hi = __uint_as_float(h);
    lo = __uint_as_float(to_tf32(z - hi));
}

#define MMA_TF32(d, a, b0_, b1_) \
    asm volatile("mma.sync.aligned.m16n8k8.row.col.f32.tf32.tf32.f32 " \
        "{%0,%1,%2,%3}, {%4,%5,%6,%7}, {%8,%9}, {%0,%1,%2,%3};" \
        : "+f"((d)[0]), "+f"((d)[1]), "+f"((d)[2]), "+f"((d)[3]) \
        : "r"((a)[0]), "r"((a)[1]), "r"((a)[2]), "r"((a)[3]), \
          "r"(b0_), "r"(b1_))

__global__ void __launch_bounds__(256)
k_gemm(int phase, const float* __restrict__ epsPtr,
       const float* __restrict__ W, const float* __restrict__ bias,
       float* __restrict__ C2, int c2off) {
    extern __shared__ float sm[];
    float* Ahs = sm;                      // [128][PADA]
    float* Als = Ahs + 128 * PADA;
    float* Bhs = Als + 128 * PADA;        // [64][PADB]
    float* Bls = Bhs + 64 * PADB;
    __shared__ float sbias[128];

    int tid = threadIdx.x;
    if (tid < 128) sbias[tid] = __ldg(bias + tid);

    int row0 = blockIdx.x * 128;
    int warp = tid >> 5, lane = tid & 31;
    int m_block = warp >> 1;        // 0..3 -> 32 rows each
    int n_block = warp & 1;         // 0..1 -> 64 cols each
    int g2 = lane >> 2, t4 = lane & 3;

    // staging ids: each thread owns half a row of A (32 k values)
    int sr = tid >> 1;
    int sks = (tid & 1) * 32;
    int grow_s = row0 + sr;
    bool valid_s = grow_s < Nn;
    float ep = 1.0f, idg = 0.0f;
    if (phase == 0) {
        ep = 1.0f + __ldg(epsPtr);
        idg = valid_s ? g_invdeg[grow_s] : 0.0f;
    }
    const float* Asrc = phase ? g_tmp : g_h;

    float acc[2][8][4];
    #pragma unroll
    for (int mt = 0; mt < 2; mt++)
        #pragma unroll
        for (int nt = 0; nt < 8; nt++)
            #pragma unroll
            for (int q = 0; q < 4; q++) acc[mt][nt][q] = 0.0f;

    #pragma unroll 1
    for (int c = 0; c < 2; c++) {
        int K0 = c * 64;
        __syncthreads();   // previous-chunk readers done before overwrite
        // ---- stage A hi/lo ----
        {
            const float* Ar = Asrc + (size_t)grow_s * Hh + K0 + sks;
            const float* Gr = g_agg + (size_t)grow_s * Hh + K0 + sks;
            #pragma unroll
            for (int kk = 0; kk < 32; kk += 4) {
                float4 v = make_float4(0.f, 0.f, 0.f, 0.f);
                if (valid_s) {
                    v = *(const float4*)(Ar + kk);
                    if (phase == 0) {
                        float4 a4 = *(const float4*)(Gr + kk);
                        v.x = fmaf(ep, v.x, a4.x * idg);
                        v.y = fmaf(ep, v.y, a4.y * idg);
                        v.z = fmaf(ep, v.z, a4.z * idg);
                        v.w = fmaf(ep, v.w, a4.w * idg);
                    }
                }
                float4 hi, lo;
                split_tf32(v.x, hi.x, lo.x);
                split_tf32(v.y, hi.y, lo.y);
                split_tf32(v.z, hi.z, lo.z);
                split_tf32(v.w, hi.w, lo.w);
                *(float4*)&Ahs[sr * PADA + sks + kk] = hi;
                *(float4*)&Als[sr * PADA + sks + kk] = lo;
            }
        }
        // ---- stage B hi/lo (W rows K0..K0+63, coalesced along n) ----
        {
            int n4 = (tid & 31) * 4;
            int kb = tid >> 5;
            #pragma unroll
            for (int i = 0; i < 8; i++) {
                int kk = kb + i * 8;
                float4 w = *(const float4*)(W + (size_t)(K0 + kk) * Hh + n4);
                float4 hi, lo;
                split_tf32(w.x, hi.x, lo.x);
                split_tf32(w.y, hi.y, lo.y);
                split_tf32(w.z, hi.z, lo.z);
                split_tf32(w.w, hi.w, lo.w);
                *(float4*)&Bhs[kk * PADB + n4] = hi;
                *(float4*)&Bls[kk * PADB + n4] = lo;
            }
        }
        __syncthreads();
        // ---- compute ----
        #pragma unroll
        for (int k8 = 0; k8 < 8; k8++) {
            uint32_t ah[2][4], al[2][4];
            #pragma unroll
            for (int mt = 0; mt < 2; mt++) {
                int r = m_block * 32 + mt * 16 + g2;
                int col = k8 * 8 + t4;
                ah[mt][0] = __float_as_uint(Ahs[r * PADA + col]);
                ah[mt][1] = __float_as_uint(Ahs[(r + 8) * PADA + col]);
                ah[mt][2] = __float_as_uint(Ahs[r * PADA + col + 4]);
                ah[mt][3] = __float_as_uint(Ahs[(r + 8) * PADA + col + 4]);
                al[mt][0] = __float_as_uint(Als[r * PADA + col]);
                al[mt][1] = __float_as_uint(Als[(r + 8) * PADA + col]);
                al[mt][2] = __float_as_uint(Als[r * PADA + col + 4]);
                al[mt][3] = __float_as_uint(Als[(r + 8) * PADA + col + 4]);
            }
            #pragma unroll
            for (int nt = 0; nt < 8; nt++) {
                int bn = n_block * 64 + nt * 8 + g2;
                int bk = k8 * 8 + t4;
                uint32_t bh0 = __float_as_uint(Bhs[bk * PADB + bn]);
                uint32_t bh1 = __float_as_uint(Bhs[(bk + 4) * PADB + bn]);
                uint32_t bl0 = __float_as_uint(Bls[bk * PADB + bn]);
                uint32_t bl1 = __float_as_uint(Bls[(bk + 4) * PADB + bn]);
                #pragma unroll
                for (int mt = 0; mt < 2; mt++) {
                    MMA_TF32(acc[mt][nt], ah[mt], bh0, bh1);
                    MMA_TF32(acc[mt][nt], al[mt], bh0, bh1);
                    MMA_TF32(acc[mt][nt], ah[mt], bl0, bl1);
                }
            }
        }
    }

    // ---- epilogue ----
    float* Cp = phase ? g_h : g_tmp;
    int do_relu = (phase == 0);
    #pragma unroll
    for (int mt = 0; mt < 2; mt++) {
        int r_lo = row0 + m_block * 32 + mt * 16 + g2;
        int r_hi = r_lo + 8;
        #pragma unroll
        for (int nt = 0; nt < 8; nt++) {
            int cc = n_block * 64 + nt * 8 + t4 * 2;
            float b0 = sbias[cc], b1 = sbias[cc + 1];
            float2 o0 = make_float2(acc[mt][nt][0] + b0, acc[mt][nt][1] + b1);
            float2 o1 = make_float2(acc[mt][nt][2] + b0, acc[mt][nt][3] + b1);
            if (do_relu) {
                o0.x = fmaxf(o0.x, 0.f); o0.y = fmaxf(o0.y, 0.f);
                o1.x = fmaxf(o1.x, 0.f); o1.y = fmaxf(o1.y, 0.f);
            }
            if (r_lo < Nn) {
                *(float2*)(Cp + (size_t)r_lo * Hh + cc) = o0;
                if (C2) *(float2*)(C2 + (size_t)r_lo * (Ll * Hh) + c2off + cc) = o0;
            }
            if (r_hi < Nn) {
                *(float2*)(Cp + (size_t)r_hi * Hh + cc) = o1;
                if (C2) *(float2*)(C2 + (size_t)r_hi * (Ll * Hh) + c2off + cc) = o1;
            }
        }
    }
}

// ---------------- vt[g] = sum_{n in graph g} h[n] + vn[g] -------------------
__global__ void k_vt() {
    int g = blockIdx.x;
    int c = threadIdx.x;   // 128 threads
    int s = g_starts[g], e = g_starts[g + 1];
    float acc = 0.0f;
    int n = s;
    for (; n + 4 <= e; n += 4) {
        acc += __ldg(&g_h[(size_t)(n + 0) * Hh + c]);
        acc += __ldg(&g_h[(size_t)(n + 1) * Hh + c]);
        acc += __ldg(&g_h[(size_t)(n + 2) * Hh + c]);
        acc += __ldg(&g_h[(size_t)(n + 3) * Hh + c]);
    }
    for (; n < e; n++) acc += __ldg(&g_h[(size_t)n * Hh + c]);
    g_vt[g * Hh + c] = acc + g_vn[g * Hh + c];
}

// ---------------- virtual-node two-layer MLP (fused) ------------------------
__global__ void k_vnmlp(const float* __restrict__ W1, const float* __restrict__ b1,
                        const float* __restrict__ W2, const float* __restrict__ b2) {
    __shared__ float vrow[128];
    __shared__ float trow[128];
    int g = blockIdx.x, c = threadIdx.x;
    vrow[c] = g_vt[g * Hh + c];
    __syncthreads();
    float acc = __ldg(b1 + c);
    #pragma unroll 8
    for (int k = 0; k < 128; k++) acc = fmaf(vrow[k], __ldg(W1 + k * 128 + c), acc);
    trow[c] = fmaxf(acc, 0.0f);
    __syncthreads();
    float acc2 = __ldg(b2 + c);
    #pragma unroll 8
    for (int k = 0; k < 128; k++) acc2 = fmaf(trow[k], __ldg(W2 + k * 128 + c), acc2);
    g_vn[g * Hh + c] = fmaxf(acc2, 0.0f);
}

// ---------------- launcher ---------------------------------------------------
extern "C" void kernel_launch(void* const* d_in, const int* in_sizes, int n_in,
                              void* d_out, int out_size) {
    const float* x         = (const float*)d_in[0];
    const float* edge_attr = (const float*)d_in[1];
    const float* conv_W1   = (const float*)d_in[2];
    const float* conv_b1   = (const float*)d_in[3];
    const float* conv_W2   = (const float*)d_in[4];
    const float* conv_b2   = (const float*)d_in[5];
    const float* conv_eps  = (const float*)d_in[6];
    const float* edge_W    = (const float*)d_in[7];
    const float* edge_b    = (const float*)d_in[8];
    const float* vn_W1     = (const float*)d_in[9];
    const float* vn_b1     = (const float*)d_in[10];
    const float* vn_W2     = (const float*)d_in[11];
    const float* vn_b2     = (const float*)d_in[12];
    const float* vn_emb    = (const float*)d_in[13];
    const int*   edge_index= (const int*)d_in[14];
    const int*   batch     = (const int*)d_in[15];
    float* out = (float*)d_out;

    (void)in_sizes; (void)n_in; (void)out_size;

    void *p_deg = nullptr, *p_agg = nullptr;
    cudaGetSymbolAddress(&p_deg, g_deg);
    cudaGetSymbolAddress(&p_agg, g_agg);

    const int smem_bytes = (2 * 128 * PADA + 2 * 64 * PADB) * (int)sizeof(float);
    cudaFuncSetAttribute(k_gemm, cudaFuncAttributeMaxDynamicSharedMemorySize,
                         smem_bytes);

    cudaMemsetAsync(p_deg, 0, Nn * sizeof(int), 0);
    k_deg<<<(Ee + 255) / 256, 256>>>(edge_index + Ee);
    k_setup<<<(Nn + 255) / 256, 256>>>(batch, vn_emb);

    const int gemm_grid = (Nn + 127) / 128;

    for (int i = 0; i < Ll; i++) {
        k_addvn<<<(Nn * 32 + 255) / 256, 256>>>(x, batch, i == 0 ? 1 : 0);
        cudaMemsetAsync(p_agg, 0, (size_t)Nn * Hh * sizeof(float), 0);
        k_edge<<<(Ee + 7) / 8, 256>>>(edge_index, edge_attr,
                                      edge_W + i * Hh, edge_b + i * Hh);
        k_gemm<<<gemm_grid, 256, smem_bytes>>>(0, conv_eps + i,
                                               conv_W1 + (size_t)i * Hh * Hh,
                                               conv_b1 + i * Hh, nullptr, 0);
        k_gemm<<<gemm_grid, 256, smem_bytes>>>(1, conv_eps + i,
                                               conv_W2 + (size_t)i * Hh * Hh,
                                               conv_b2 + i * Hh, out, i * Hh);
        if (i < Ll - 1) {
            k_vt<<<Gg, Hh>>>();
            k_vnmlp<<<Gg, Hh>>>(vn_W1 + (size_t)i * Hh * Hh, vn_b1 + i * Hh,
                                vn_W2 + (size_t)i * Hh * Hh, vn_b2 + i * Hh);
        }
    }
}

// round 4
// speedup vs baseline: 1.6250x; 1.5226x over previous
#include <cuda_runtime.h>
#include <cstdint>

#define Nn 50000
#define Ee 800000
#define Hh 128
#define Ll 4
#define Gg 64
#define NB 196   // (Nn+255)/256 scan blocks

// ---------------- scratch (device globals; no allocation allowed) ----------
__device__ float g_h[(size_t)Nn * Hh];     // current node features
__device__ float g_tmp[(size_t)Nn * Hh];   // MLP intermediate
__device__ float g_agg[(size_t)Nn * Hh];   // mean-aggregated messages
__device__ float g_invdeg[Nn];
__device__ int   g_deg[Nn];
__device__ float g_vn[Gg * Hh];
__device__ float g_vt[Gg * Hh];
__device__ int   g_off[Nn + 1];
__device__ int   g_cursor[Nn];
__device__ int   g_bsum[256];
__device__ int   g_bpre[256];
__device__ float2 g_csr[Ee];               // {src_as_float, attr} grouped by tgt

// ---------------- degree histogram ------------------------------------------
__global__ void k_deg(const int* __restrict__ tgt) {
    int e = blockIdx.x * blockDim.x + threadIdx.x;
    if (e < Ee) atomicAdd(&g_deg[__ldg(tgt + e)], 1);
}

// ---------------- setup: invdeg + vn init -----------------------------------
__global__ void k_setup(const float* __restrict__ vn_emb) {
    int n = blockIdx.x * blockDim.x + threadIdx.x;
    if (n < Nn) {
        int d = g_deg[n];
        g_invdeg[n] = 1.0f / (float)(d > 0 ? d : 1);
    }
    if (n < Gg * Hh) g_vn[n] = __ldg(vn_emb + (n & (Hh - 1)));
}

// ---------------- 3-kernel exclusive scan of g_deg -> g_off -----------------
__global__ void k_scan1() {
    __shared__ int s[256];
    int n = blockIdx.x * 256 + threadIdx.x;
    int d = (n < Nn) ? g_deg[n] : 0;
    s[threadIdx.x] = d;
    __syncthreads();
    for (int off = 128; off > 0; off >>= 1) {
        if (threadIdx.x < off) s[threadIdx.x] += s[threadIdx.x + off];
        __syncthreads();
    }
    if (threadIdx.x == 0) g_bsum[blockIdx.x] = s[0];
}
__global__ void k_scan2() {
    __shared__ int s[256];
    int tid = threadIdx.x;
    int v = (tid < NB) ? g_bsum[tid] : 0;
    s[tid] = v;
    __syncthreads();
    for (int off = 1; off < 256; off <<= 1) {
        int t = (tid >= off) ? s[tid - off] : 0;
        __syncthreads();
        s[tid] += t;
        __syncthreads();
    }
    if (tid < NB) g_bpre[tid] = s[tid] - v;   // exclusive
}
__global__ void k_scan3() {
    __shared__ int s[256];
    int tid = threadIdx.x;
    int n = blockIdx.x * 256 + tid;
    int d = (n < Nn) ? g_deg[n] : 0;
    s[tid] = d;
    __syncthreads();
    for (int off = 1; off < 256; off <<= 1) {
        int t = (tid >= off) ? s[tid - off] : 0;
        __syncthreads();
        s[tid] += t;
        __syncthreads();
    }
    if (n < Nn) {
        int excl = s[tid] - d + g_bpre[blockIdx.x];
        g_off[n] = excl;
        g_cursor[n] = excl;
    }
    if (blockIdx.x == 0 && tid == 0) g_off[Nn] = Ee;
}

// ---------------- scatter edges into CSR buckets ----------------------------
__global__ void k_scatter(const int* __restrict__ ei,
                          const float* __restrict__ eattr) {
    int e = blockIdx.x * blockDim.x + threadIdx.x;
    if (e >= Ee) return;
    int s = __ldg(ei + e);
    int t = __ldg(ei + Ee + e);
    int p = atomicAdd(&g_cursor[t], 1);
    g_csr[p] = make_float2(__int_as_float(s), __ldg(eattr + e));
}

// ---------------- h = src + vn[batch] ---------------------------------------
__global__ void k_addvn(const float* __restrict__ xin,
                        const int* __restrict__ batch, int use_x) {
    int i = blockIdx.x * blockDim.x + threadIdx.x;
    if (i >= Nn * 32) return;
    int n = i >> 5;
    int q = (i & 31) * 4;
    const float* srcp = use_x ? xin : g_h;
    int b = __ldg(batch + n);
    float4 v = *(const float4*)(srcp + (size_t)n * Hh + q);
    float4 w = *(const float4*)(g_vn + b * Hh + q);
    v.x += w.x; v.y += w.y; v.z += w.z; v.w += w.w;
    *(float4*)(g_h + (size_t)n * Hh + q) = v;
}

// ---------------- CSR mean aggregation: one warp per node -------------------
__device__ __forceinline__ void msg_acc(float4& acc, const float4 h4, float a,
                                        const float4 w, const float4 bb) {
    acc.x += fmaxf(h4.x + fmaf(a, w.x, bb.x), 0.0f);
    acc.y += fmaxf(h4.y + fmaf(a, w.y, bb.y), 0.0f);
    acc.z += fmaxf(h4.z + fmaf(a, w.z, bb.z), 0.0f);
    acc.w += fmaxf(h4.w + fmaf(a, w.w, bb.w), 0.0f);
}

__global__ void k_agg(const float* __restrict__ eW,
                      const float* __restrict__ eb) {
    int n = (blockIdx.x * blockDim.x + threadIdx.x) >> 5;
    if (n >= Nn) return;
    int lane = threadIdx.x & 31;
    int q = lane * 4;
    float4 w  = *(const float4*)(eW + q);
    float4 bb = *(const float4*)(eb + q);
    int j0 = g_off[n], j1 = g_off[n + 1];
    float4 acc = make_float4(0.f, 0.f, 0.f, 0.f);
    int j = j0;
    for (; j + 4 <= j1; j += 4) {
        float2 e0 = __ldg(&g_csr[j + 0]);
        float2 e1 = __ldg(&g_csr[j + 1]);
        float2 e2 = __ldg(&g_csr[j + 2]);
        float2 e3 = __ldg(&g_csr[j + 3]);
        float4 h0 = *(const float4*)(g_h + (size_t)__float_as_int(e0.x) * Hh + q);
        float4 h1 = *(const float4*)(g_h + (size_t)__float_as_int(e1.x) * Hh + q);
        float4 h2 = *(const float4*)(g_h + (size_t)__float_as_int(e2.x) * Hh + q);
        float4 h3 = *(const float4*)(g_h + (size_t)__float_as_int(e3.x) * Hh + q);
        msg_acc(acc, h0, e0.y, w, bb);
        msg_acc(acc, h1, e1.y, w, bb);
        msg_acc(acc, h2, e2.y, w, bb);
        msg_acc(acc, h3, e3.y, w, bb);
    }
    for (; j < j1; j++) {
        float2 e0 = __ldg(&g_csr[j]);
        float4 h0 = *(const float4*)(g_h + (size_t)__float_as_int(e0.x) * Hh + q);
        msg_acc(acc, h0, e0.y, w, bb);
    }
    float idg = g_invdeg[n];
    acc.x *= idg; acc.y *= idg; acc.z *= idg; acc.w *= idg;
    *(float4*)(g_agg + (size_t)n * Hh + q) = acc;
}

// ================= 3xTF32 split GEMM via mma.sync ===========================
// K staged in 4 chunks of 32. SMEM ~71.7KB -> 2 CTAs/SM.
#define KCH  32
#define PADA 36    // 36 mod 32 = 4 -> conflict-free A frag LDS
#define PADB 136   // 136 mod 32 = 8 -> conflict-free B frag LDS

__device__ __forceinline__ uint32_t to_tf32(float z) {
    uint32_t h;
    asm("cvt.rna.tf32.f32 %0, %1;" : "=r"(h) : "f"(z));
    return h;
}
__device__ __forceinline__ void split_tf32(float z, float& hi, float& lo) {
    uint32_t h = to_tf32(z);
    hi = __uint_as_float(h);
    lo = __uint_as_float(to_tf32(z - hi));
}

#define MMA_TF32(d, a, b0_, b1_) \
    asm volatile("mma.sync.aligned.m16n8k8.row.col.f32.tf32.tf32.f32 " \
        "{%0,%1,%2,%3}, {%4,%5,%6,%7}, {%8,%9}, {%0,%1,%2,%3};" \
        : "+f"((d)[0]), "+f"((d)[1]), "+f"((d)[2]), "+f"((d)[3]) \
        : "r"((a)[0]), "r"((a)[1]), "r"((a)[2]), "r"((a)[3]), \
          "r"(b0_), "r"(b1_))

__global__ void __launch_bounds__(256, 2)
k_gemm(int phase, const float* __restrict__ epsPtr,
       const float* __restrict__ W, const float* __restrict__ bias,
       float* __restrict__ C2, int c2off) {
    extern __shared__ float sm[];
    float* Ahs = sm;                       // [128][PADA]
    float* Als = Ahs + 128 * PADA;
    float* Bhs = Als + 128 * PADA;         // [KCH][PADB]
    float* Bls = Bhs + KCH * PADB;
    __shared__ float sbias[128];

    int tid = threadIdx.x;
    if (tid < 128) sbias[tid] = __ldg(bias + tid);

    int row0 = blockIdx.x * 128;
    int warp = tid >> 5, lane = tid & 31;
    int m_block = warp >> 1;
    int n_block = warp & 1;
    int g2 = lane >> 2, t4 = lane & 3;

    // A staging: thread owns half a row (16 k values) per chunk
    int sr = tid >> 1;
    int sks = (tid & 1) * 16;
    int grow_s = row0 + sr;
    bool valid_s = grow_s < Nn;
    float ep = 1.0f;
    if (phase == 0) ep = 1.0f + __ldg(epsPtr);
    const float* Asrc = phase ? g_tmp : g_h;

    float acc[2][8][4];
    #pragma unroll
    for (int mt = 0; mt < 2; mt++)
        #pragma unroll
        for (int nt = 0; nt < 8; nt++)
            #pragma unroll
            for (int q = 0; q < 4; q++) acc[mt][nt][q] = 0.0f;

    #pragma unroll 1
    for (int c = 0; c < 4; c++) {
        int K0 = c * KCH;
        __syncthreads();
        // ---- stage A hi/lo (fused (1+eps)h + agg_mean in phase 0) ----
        {
            const float* Ar = Asrc + (size_t)grow_s * Hh + K0 + sks;
            const float* Gr = g_agg + (size_t)grow_s * Hh + K0 + sks;
            #pragma unroll
            for (int kk = 0; kk < 16; kk += 4) {
                float4 v = make_float4(0.f, 0.f, 0.f, 0.f);
                if (valid_s) {
                    v = *(const float4*)(Ar + kk);
                    if (phase == 0) {
                        float4 a4 = *(const float4*)(Gr + kk);
                        v.x = fmaf(ep, v.x, a4.x);
                        v.y = fmaf(ep, v.y, a4.y);
                        v.z = fmaf(ep, v.z, a4.z);
                        v.w = fmaf(ep, v.w, a4.w);
                    }
                }
                float4 hi, lo;
                split_tf32(v.x, hi.x, lo.x);
                split_tf32(v.y, hi.y, lo.y);
                split_tf32(v.z, hi.z, lo.z);
                split_tf32(v.w, hi.w, lo.w);
                *(float4*)&Ahs[sr * PADA + sks + kk] = hi;
                *(float4*)&Als[sr * PADA + sks + kk] = lo;
            }
        }
        // ---- stage B hi/lo: W rows K0..K0+31 ----
        {
            int n4 = (tid & 31) * 4;
            int kb = tid >> 5;
            #pragma unroll
            for (int i = 0; i < 4; i++) {
                int kk = kb + i * 8;
                float4 w = *(const float4*)(W + (size_t)(K0 + kk) * Hh + n4);
                float4 hi, lo;
                split_tf32(w.x, hi.x, lo.x);
                split_tf32(w.y, hi.y, lo.y);
                split_tf32(w.z, hi.z, lo.z);
                split_tf32(w.w, hi.w, lo.w);
                *(float4*)&Bhs[kk * PADB + n4] = hi;
                *(float4*)&Bls[kk * PADB + n4] = lo;
            }
        }
        __syncthreads();
        // ---- compute ----
        #pragma unroll
        for (int k8 = 0; k8 < 4; k8++) {
            uint32_t ah[2][4], al[2][4];
            #pragma unroll
            for (int mt = 0; mt < 2; mt++) {
                int r = m_block * 32 + mt * 16 + g2;
                int col = k8 * 8 + t4;
                ah[mt][0] = __float_as_uint(Ahs[r * PADA + col]);
                ah[mt][1] = __float_as_uint(Ahs[(r + 8) * PADA + col]);
                ah[mt][2] = __float_as_uint(Ahs[r * PADA + col + 4]);
                ah[mt][3] = __float_as_uint(Ahs[(r + 8) * PADA + col + 4]);
                al[mt][0] = __float_as_uint(Als[r * PADA + col]);
                al[mt][1] = __float_as_uint(Als[(r + 8) * PADA + col]);
                al[mt][2] = __float_as_uint(Als[r * PADA + col + 4]);
                al[mt][3] = __float_as_uint(Als[(r + 8) * PADA + col + 4]);
            }
            #pragma unroll
            for (int nt = 0; nt < 8; nt++) {
                int bn = n_block * 64 + nt * 8 + g2;
                int bk = k8 * 8 + t4;
                uint32_t bh0 = __float_as_uint(Bhs[bk * PADB + bn]);
                uint32_t bh1 = __float_as_uint(Bhs[(bk + 4) * PADB + bn]);
                uint32_t bl0 = __float_as_uint(Bls[bk * PADB + bn]);
                uint32_t bl1 = __float_as_uint(Bls[(bk + 4) * PADB + bn]);
                #pragma unroll
                for (int mt = 0; mt < 2; mt++) {
                    MMA_TF32(acc[mt][nt], ah[mt], bh0, bh1);
                    MMA_TF32(acc[mt][nt], al[mt], bh0, bh1);
                    MMA_TF32(acc[mt][nt], ah[mt], bl0, bl1);
                }
            }
        }
    }

    // ---- epilogue ----
    float* Cp = phase ? g_h : g_tmp;
    int do_relu = (phase == 0);
    #pragma unroll
    for (int mt = 0; mt < 2; mt++) {
        int r_lo = row0 + m_block * 32 + mt * 16 + g2;
        int r_hi = r_lo + 8;
        #pragma unroll
        for (int nt = 0; nt < 8; nt++) {
            int cc = n_block * 64 + nt * 8 + t4 * 2;
            float b0 = sbias[cc], b1 = sbias[cc + 1];
            float2 o0 = make_float2(acc[mt][nt][0] + b0, acc[mt][nt][1] + b1);
            float2 o1 = make_float2(acc[mt][nt][2] + b0, acc[mt][nt][3] + b1);
            if (do_relu) {
                o0.x = fmaxf(o0.x, 0.f); o0.y = fmaxf(o0.y, 0.f);
                o1.x = fmaxf(o1.x, 0.f); o1.y = fmaxf(o1.y, 0.f);
            }
            if (r_lo < Nn) {
                *(float2*)(Cp + (size_t)r_lo * Hh + cc) = o0;
                if (C2) *(float2*)(C2 + (size_t)r_lo * (Ll * Hh) + c2off + cc) = o0;
            }
            if (r_hi < Nn) {
                *(float2*)(Cp + (size_t)r_hi * Hh + cc) = o1;
                if (C2) *(float2*)(C2 + (size_t)r_hi * (Ll * Hh) + c2off + cc) = o1;
            }
        }
    }
}

// ---------------- vt: init + parallel partial sums --------------------------
__global__ void k_vtinit() {
    int i = blockIdx.x * blockDim.x + threadIdx.x;
    if (i < Gg * Hh) g_vt[i] = g_vn[i];
}

__global__ void k_vtadd(const int* __restrict__ batch) {
    int row0 = blockIdx.x * 128;
    int c = threadIdx.x;
    int end = row0 + 128; if (end > Nn) end = Nn;
    if (row0 >= Nn) return;
    int gfirst = __ldg(batch + row0);
    int glast  = __ldg(batch + end - 1);
    if (gfirst == glast) {
        float acc = 0.0f;
        #pragma unroll 4
        for (int n = row0; n < end; n++) acc += g_h[(size_t)n * Hh + c];
        atomicAdd(&g_vt[gfirst * Hh + c], acc);
    } else {
        float acc = 0.0f;
        int cur = gfirst;
        for (int n = row0; n < end; n++) {
            int g = __ldg(batch + n);
            if (g != cur) {
                atomicAdd(&g_vt[cur * Hh + c], acc);
                cur = g; acc = 0.0f;
            }
            acc += g_h[(size_t)n * Hh + c];
        }
        atomicAdd(&g_vt[cur * Hh + c], acc);
    }
}

// ---------------- virtual-node two-layer MLP (fused) ------------------------
__global__ void k_vnmlp(const float* __restrict__ W1, const float* __restrict__ b1,
                        const float* __restrict__ W2, const float* __restrict__ b2) {
    __shared__ float vrow[128];
    __shared__ float trow[128];
    int g = blockIdx.x, c = threadIdx.x;
    vrow[c] = g_vt[g * Hh + c];
    __syncthreads();
    float acc = __ldg(b1 + c);
    #pragma unroll 8
    for (int k = 0; k < 128; k++) acc = fmaf(vrow[k], __ldg(W1 + k * 128 + c), acc);
    trow[c] = fmaxf(acc, 0.0f);
    __syncthreads();
    float acc2 = __ldg(b2 + c);
    #pragma unroll 8
    for (int k = 0; k < 128; k++) acc2 = fmaf(trow[k], __ldg(W2 + k * 128 + c), acc2);
    g_vn[g * Hh + c] = fmaxf(acc2, 0.0f);
}

// ---------------- launcher ---------------------------------------------------
extern "C" void kernel_launch(void* const* d_in, const int* in_sizes, int n_in,
                              void* d_out, int out_size) {
    const float* x         = (const float*)d_in[0];
    const float* edge_attr = (const float*)d_in[1];
    const float* conv_W1   = (const float*)d_in[2];
    const float* conv_b1   = (const float*)d_in[3];
    const float* conv_W2   = (const float*)d_in[4];
    const float* conv_b2   = (const float*)d_in[5];
    const float* conv_eps  = (const float*)d_in[6];
    const float* edge_W    = (const float*)d_in[7];
    const float* edge_b    = (const float*)d_in[8];
    const float* vn_W1     = (const float*)d_in[9];
    const float* vn_b1     = (const float*)d_in[10];
    const float* vn_W2     = (const float*)d_in[11];
    const float* vn_b2     = (const float*)d_in[12];
    const float* vn_emb    = (const float*)d_in[13];
    const int*   edge_index= (const int*)d_in[14];
    const int*   batch     = (const int*)d_in[15];
    float* out = (float*)d_out;

    (void)in_sizes; (void)n_in; (void)out_size;

    void* p_deg = nullptr;
    cudaGetSymbolAddress(&p_deg, g_deg);

    const int smem_bytes =
        (2 * 128 * PADA + 2 * KCH * PADB) * (int)sizeof(float);
    cudaFuncSetAttribute(k_gemm, cudaFuncAttributeMaxDynamicSharedMemorySize,
                         smem_bytes);

    // ---- CSR build (per call; edge structure fixed) ----
    cudaMemsetAsync(p_deg, 0, Nn * sizeof(int), 0);
    k_deg<<<(Ee + 255) / 256, 256>>>(edge_index + Ee);
    k_setup<<<(Nn + 255) / 256, 256>>>(vn_emb);
    k_scan1<<<NB, 256>>>();
    k_scan2<<<1, 256>>>();
    k_scan3<<<NB, 256>>>();
    k_scatter<<<(Ee + 255) / 256, 256>>>(edge_index, edge_attr);

    const int gemm_grid = (Nn + 127) / 128;
    const int agg_grid  = (Nn * 32 + 255) / 256;

    for (int i = 0; i < Ll; i++) {
        k_addvn<<<(Nn * 32 + 255) / 256, 256>>>(x, batch, i == 0 ? 1 : 0);
        k_agg<<<agg_grid, 256>>>(edge_W + i * Hh, edge_b + i * Hh);
        k_gemm<<<gemm_grid, 256, smem_bytes>>>(0, conv_eps + i,
                                               conv_W1 + (size_t)i * Hh * Hh,
                                               conv_b1 + i * Hh, nullptr, 0);
        k_gemm<<<gemm_grid, 256, smem_bytes>>>(1, conv_eps + i,
                                               conv_W2 + (size_t)i * Hh * Hh,
                                               conv_b2 + i * Hh, out, i * Hh);
        if (i < Ll - 1) {
            k_vtinit<<<(Gg * Hh + 255) / 256, 256>>>();
            k_vtadd<<<gemm_grid, 128>>>(batch);
            k_vnmlp<<<Gg, Hh>>>(vn_W1 + (size_t)i * Hh * Hh, vn_b1 + i * Hh,
                                vn_W2 + (size_t)i * Hh * Hh, vn_b2 + i * Hh);
        }
    }
}